// round 1
// baseline (speedup 1.0000x reference)
#include <cuda_runtime.h>
#include <cstdint>

// DCT_Layer: grouped conv with fixed separable 4x4 DCT basis, padding=2,
// followed by min(|v|, 8).
// x: (8, 3, 512, 512) f32  ->  out: (8, 48, 513, 513) f32
//
// Separable basis: k[kk*4+ll][i][j] = A[kk][i] * A[ll][j]
//   A[0][i] = 0.5
//   A[k][i] = sqrt(0.5) * cos(pi/8 * k * (2i+1))   (k=1..3)

#define HIN   512
#define WIN   512
#define HOUT  513
#define WOUT  513
#define PLANE (HOUT * WOUT)   // 263169
#define TX    128             // output columns per block

__constant__ float c_A[4][4] = {
    { 0.5f,                  0.5f,                  0.5f,                  0.5f                 },
    { 0.65328148243818826f,  0.27059805007309851f, -0.27059805007309851f, -0.65328148243818826f },
    { 0.5f,                 -0.5f,                 -0.5f,                  0.5f                 },
    { 0.27059805007309851f, -0.65328148243818826f,  0.65328148243818826f, -0.27059805007309851f }
};

__global__ __launch_bounds__(TX, 8)
void dct_layer_kernel(const float* __restrict__ x, float* __restrict__ out) {
    const int bc    = blockIdx.z;          // b*3 + c   (0..23)
    const int y     = blockIdx.y;          // output row (0..512)
    const int xbase = blockIdx.x * TX;     // output col base
    const int t     = threadIdx.x;

    __shared__ float xin[4][TX + 4];       // 4 input rows, TX+3 cols used
    __shared__ float s[4][TX + 4];         // column-DCT result per kk

    const float* __restrict__ xp = x + (size_t)bc * HIN * WIN;

    // ---- cooperative load: rows y-2..y+1, cols xbase-2..xbase+TX (TX+3 cols)
    const int NCOL = TX + 3;
    for (int idx = t; idx < 4 * NCOL; idx += TX) {
        int i  = idx / NCOL;
        int xi = idx - i * NCOL;
        int iy = y - 2 + i;
        int ix = xbase - 2 + xi;
        float v = 0.0f;
        if ((unsigned)iy < (unsigned)HIN && (unsigned)ix < (unsigned)WIN)
            v = xp[iy * WIN + ix];
        xin[i][xi] = v;
    }
    __syncthreads();

    // ---- column pass: s[kk][xi] = sum_i A[kk][i] * xin[i][xi]
    for (int xi = t; xi < NCOL; xi += TX) {
        float v0 = xin[0][xi], v1 = xin[1][xi], v2 = xin[2][xi], v3 = xin[3][xi];
        // kk = 0: 0.5*(v0+v1+v2+v3)
        s[0][xi] = 0.5f * ((v0 + v3) + (v1 + v2));
        s[1][xi] = c_A[1][0] * (v0 - v3) + c_A[1][1] * (v1 - v2);
        s[2][xi] = 0.5f * ((v0 + v3) - (v1 + v2));
        s[3][xi] = c_A[3][0] * (v1 - v2) * (-1.0f) + c_A[1][0] * 0.0f  // placeholder, replaced below
                 ;
        // A[3] = {A13, -A11, A11, -A13} with A11=c_A[1][0], A13=c_A[1][1]
        s[3][xi] = c_A[1][1] * (v0 - v3) - c_A[1][0] * (v1 - v2);
    }
    __syncthreads();

    // ---- row pass + |.| clamp + store
    const int xo = xbase + t;
    if (xo < WOUT) {
        float sv[4][4];
#pragma unroll
        for (int kk = 0; kk < 4; kk++)
#pragma unroll
            for (int j = 0; j < 4; j++)
                sv[kk][j] = s[kk][t + j];

        float* __restrict__ op = out + (size_t)bc * 16 * PLANE + (size_t)y * WOUT + xo;
#pragma unroll
        for (int kk = 0; kk < 4; kk++) {
            const float p03 = sv[kk][0] + sv[kk][3];
            const float p12 = sv[kk][1] + sv[kk][2];
            const float m03 = sv[kk][0] - sv[kk][3];
            const float m12 = sv[kk][1] - sv[kk][2];
            float r0 = 0.5f * (p03 + p12);
            float r1 = c_A[1][0] * m03 + c_A[1][1] * m12;
            float r2 = 0.5f * (p03 - p12);
            float r3 = c_A[1][1] * m03 - c_A[1][0] * m12;
            op[(size_t)(kk * 4 + 0) * PLANE] = fminf(fabsf(r0), 8.0f);
            op[(size_t)(kk * 4 + 1) * PLANE] = fminf(fabsf(r1), 8.0f);
            op[(size_t)(kk * 4 + 2) * PLANE] = fminf(fabsf(r2), 8.0f);
            op[(size_t)(kk * 4 + 3) * PLANE] = fminf(fabsf(r3), 8.0f);
        }
    }
}

extern "C" void kernel_launch(void* const* d_in, const int* in_sizes, int n_in,
                              void* d_out, int out_size) {
    const float* x  = (const float*)d_in[0];
    float* out      = (float*)d_out;
    (void)in_sizes; (void)n_in; (void)out_size;

    dim3 grid((WOUT + TX - 1) / TX, HOUT, 8 * 3);   // (5, 513, 24)
    dim3 block(TX);
    dct_layer_kernel<<<grid, block>>>(x, out);
}